// round 14
// baseline (speedup 1.0000x reference)
#include <cuda_runtime.h>
#include <cuda_fp16.h>
#include <cstdint>

#define VOCAB 30000
#define VROWS 30080          // padded row count for partial-norm slabs
#define DIN   512
#define DH    1024
#define DOUT  2047
#define DOUTP 2048
#define NB    4096
#define SEQ   20
#define NSLAB 32             // 16 N-tiles x 2 wn warps (GEMM2)

// ---------------- scratch (__device__ globals; allocation-free rule) ----------------
__device__ int    g_flags[VOCAB];
__device__ int    g_compact[VOCAB];                // compact row -> vocab id
__device__ int    g_inv[VOCAB];                    // vocab id -> compact row
__device__ int    g_Mc;                            // number of used rows
__device__ __half g_H1c[(size_t)VOCAB * DIN];      // compact H1, fp16
__device__ __half g_W2T[(size_t)DH * DIN];         // [1024,512] N-major fp16
__device__ __half g_W3T[(size_t)DOUTP * DH];       // [2048,1024] fp16, row 2047 zero
__device__ __half g_H2c[(size_t)VOCAB * DH];       // compact H2, fp16
__device__ __half g_Ec[(size_t)VOCAB * DOUTP];     // compact E fp16, padded col 2047 == 0
__device__ float  g_nsq[(size_t)NSLAB * VROWS];    // per-slab partial sum-of-squares
__device__ float  g_invnorm[VOCAB];                // indexed by compact row

// ---------------- PTX helpers (generic PTX only; valid at compute_103) ----------------
static __device__ __forceinline__ uint32_t smem_to_u32(const void* p) {
    uint32_t a;
    asm("{ .reg .u64 t; cvta.to.shared.u64 t, %1; cvt.u32.u64 %0, t; }" : "=r"(a) : "l"(p));
    return a;
}
#define CP16(dst, src) \
    asm volatile("cp.async.cg.shared.global [%0], [%1], 16;" :: "r"(dst), "l"(src) : "memory")
#define CP_COMMIT() asm volatile("cp.async.commit_group;" ::: "memory")
#define CP_WAIT1()  asm volatile("cp.async.wait_group 1;" ::: "memory")

#define LDSM4(r0, r1, r2, r3, addr) \
    asm volatile("ldmatrix.sync.aligned.m8n8.x4.shared.b16 {%0,%1,%2,%3}, [%4];" \
        : "=r"(r0), "=r"(r1), "=r"(r2), "=r"(r3) : "r"(addr))

#define MMA_F16(d, a0, a1, a2, a3, b0, b1) \
    asm volatile("mma.sync.aligned.m16n8k16.row.col.f32.f16.f16.f32 " \
        "{%0,%1,%2,%3},{%4,%5,%6,%7},{%8,%9},{%0,%1,%2,%3};" \
        : "+f"((d)[0]), "+f"((d)[1]), "+f"((d)[2]), "+f"((d)[3]) \
        : "r"(a0), "r"(a1), "r"(a2), "r"(a3), "r"(b0), "r"(b1))

// swizzled byte offset inside a 128-row x 128-byte tile (16KB): 8 chunks of 16B per row
static __device__ __forceinline__ uint32_t swq(int row, int ch) {
    return (uint32_t)(row * 128 + ((ch ^ (row & 7)) << 4));
}
static __device__ __forceinline__ uint32_t pack_h2(float x, float y) {
    __half2 h = __floats2half2_rn(x, y);
    return *reinterpret_cast<uint32_t*>(&h);
}

// ---------------- compaction kernels ----------------
__global__ __launch_bounds__(256) void zero_flags() {
    int i = blockIdx.x * 256 + threadIdx.x;
    if (i < VOCAB) g_flags[i] = 0;
    if (i == 0) g_Mc = 0;
}
__global__ __launch_bounds__(256) void mark_used(const int* __restrict__ ingrs,
                                                 const int* __restrict__ lengths) {
    int i = blockIdx.x * 256 + threadIdx.x;
    if (i >= NB * SEQ) return;
    int b = i / SEQ, l = i - b * SEQ;
    if (l < lengths[b]) g_flags[ingrs[i]] = 1;
}
__global__ __launch_bounds__(256) void compact_ids() {
    int i = blockIdx.x * 256 + threadIdx.x;
    int flag = (i < VOCAB) ? g_flags[i] : 0;
    unsigned mask = __ballot_sync(0xffffffffu, flag);
    int lane = threadIdx.x & 31;
    int base = 0;
    if (lane == 0 && mask) base = atomicAdd(&g_Mc, __popc(mask));
    base = __shfl_sync(0xffffffffu, base, 0);
    if (flag) {
        int pos = base + __popc(mask & ((1u << lane) - 1u));
        g_compact[pos] = i;
        g_inv[i] = pos;
    }
}

// ---------------- fused prep: weight transposes + compact H1, one launch ----------------
// blocks [0,512): W2 transpose; [512,2560): W3 transpose; [2560, 2560+VOCAB/4): prep H1c.
#define PREP_TRANSPOSE_BLOCKS 2560
__global__ __launch_bounds__(256) void prep_all(const float* __restrict__ W1,
                                                const float* __restrict__ b1,
                                                const float* __restrict__ W2,
                                                const float* __restrict__ W3,
                                                __half* __restrict__ w2t,
                                                __half* __restrict__ w3t) {
    int bid = blockIdx.x;
    if (bid < PREP_TRANSPOSE_BLOCKS) {
        // -------- tiled transpose fp32 -> fp16 (rows n>=N zero) --------
        const float* src; __half* dst; int K, N, bx, by;
        if (bid < 512) { src = W2; dst = w2t; K = DIN; N = DH;   bx = bid & 31; by = bid >> 5; }
        else { bid -= 512; src = W3; dst = w3t; K = DH;  N = DOUT; bx = bid & 63; by = bid >> 6; }
        __shared__ float tile[32][33];
        const int tx = threadIdx.x & 31, ty = threadIdx.x >> 5;   // 32 x 8
        const int n0 = bx * 32, k0 = by * 32;
#pragma unroll
        for (int i = 0; i < 4; ++i) {
            int k = k0 + ty + i * 8, n = n0 + tx;
            tile[ty + i * 8][tx] = (n < N) ? src[(size_t)k * N + n] : 0.f;
        }
        __syncthreads();
#pragma unroll
        for (int i = 0; i < 4; ++i) {
            int n = n0 + ty + i * 8, k = k0 + tx;
            dst[(size_t)n * K + k] = __float2half_rn(tile[tx][ty + i * 8]);
        }
    } else {
        // -------- compact H1: 4 rows/block, MLP 2 --------
        bid -= PREP_TRANSPOSE_BLOCKS;
        const int Mc = g_Mc;
        const int r0 = bid * 4 + (threadIdx.x >> 7);          // rows 4b+{0,1}
        const int r1 = r0 + 2;                                // rows 4b+{2,3}
        if (r0 >= Mc) return;
        const int c4 = (threadIdx.x & 127) * 4;
        const int id0 = g_compact[r0];
        const int id1 = g_compact[(r1 < Mc) ? r1 : r0];       // clamp keeps load legal
        float4 w0 = __ldg(reinterpret_cast<const float4*>(&W1[(size_t)id0 * DIN + c4]));
        float4 w1 = __ldg(reinterpret_cast<const float4*>(&W1[(size_t)id1 * DIN + c4]));
        float4 bb = __ldg(reinterpret_cast<const float4*>(&b1[c4]));
        __half h0[4] = { __float2half_rn(fmaxf(w0.x + bb.x, 0.f)),
                         __float2half_rn(fmaxf(w0.y + bb.y, 0.f)),
                         __float2half_rn(fmaxf(w0.z + bb.z, 0.f)),
                         __float2half_rn(fmaxf(w0.w + bb.w, 0.f)) };
        *reinterpret_cast<uint2*>(&g_H1c[(size_t)r0 * DIN + c4]) = *reinterpret_cast<uint2*>(h0);
        if (r1 < Mc) {
            __half h1[4] = { __float2half_rn(fmaxf(w1.x + bb.x, 0.f)),
                             __float2half_rn(fmaxf(w1.y + bb.y, 0.f)),
                             __float2half_rn(fmaxf(w1.z + bb.z, 0.f)),
                             __float2half_rn(fmaxf(w1.w + bb.w, 0.f)) };
            *reinterpret_cast<uint2*>(&g_H1c[(size_t)r1 * DIN + c4]) = *reinterpret_cast<uint2*>(h1);
        }
    }
}

// ---------------- HMMA fp16 GEMM (64x64 warp tile, 4 warps, 2 CTA/SM) ----------------
// C = act(A @ B^T + bias), fp16 in/out. CTA tile 128x128, K-chunk 64,
// 3-stage cp.async pipeline (A|B @ 16KB each = 32KB/stage), 128 threads.
// Chunk-boundary LDSM bubble hidden: next chunk's kh0 frags load under kh3's MMAs.
static constexpr int STAGE_BYTES = 32768;
static constexpr int GEMM_SMEM   = 3 * STAGE_BYTES;      // 96 KB

template <bool WITH_NSQ>   // true: no relu + write norm partials; false: relu
__global__ __launch_bounds__(128, 2)
void hmma_gemm(const __half* __restrict__ Af, const __half* __restrict__ Bf,
               const float* __restrict__ bias,
               __half* __restrict__ C,
               int K, int ldc, int nbias)
{
    const int m0 = blockIdx.y * 128;
    const int Mc = g_Mc;
    if (m0 >= Mc) return;                 // uniform whole-CTA exit

    extern __shared__ __align__(128) uint8_t smem[];
    const uint32_t sbase = smem_to_u32(smem);
    const int tid  = threadIdx.x;
    const int lane = tid & 31;
    const int wid  = tid >> 5;            // 0..3
    const int wm   = wid & 1;             // m block of 64
    const int wn   = wid >> 1;            // n block of 64
    const int n0   = blockIdx.x * 128;

    const int lmat  = lane >> 3;
    const int lrow8 = ((lmat & 1) << 3) + (lane & 7);
    const int lchb  = lmat >> 1;          // 16B chunk parity within a k16

    float acc[4][8][4];
#pragma unroll
    for (int a = 0; a < 4; ++a)
#pragma unroll
        for (int b = 0; b < 8; ++b)
#pragma unroll
            for (int c = 0; c < 4; ++c) acc[a][b][c] = 0.f;

    auto load_stage = [&](int s, int k0) {
        const uint32_t base = sbase + s * STAGE_BYTES;
#pragma unroll
        for (int p = 0; p < 8; ++p) {
            int idx = p * 128 + tid;            // 0..1023
            int row = idx >> 3;                 // 0..127
            int ch  = idx & 7;                  // 16B chunk in 128B row
            uint32_t doff = swq(row, ch);
            int gm = m0 + row; if (gm > Mc - 1) gm = Mc - 1;  // clamp; rows >= Mc never stored
            CP16(base +         doff, Af + (size_t)gm * K + k0 + ch * 8);
            CP16(base + 16384 + doff, Bf + (size_t)(n0 + row) * K + k0 + ch * 8);
        }
        CP_COMMIT();
    };

    // fragment double buffers (A 4 tiles + B 4 tiles per k16)
    uint32_t afb[2][4][4], bfb[2][4][4];

    auto frag_load = [&](int set, uint32_t base, int kh) {
        const int ch = kh * 2 + lchb;
#pragma unroll
        for (int np = 0; np < 4; ++np) {
            uint32_t addr = base + 16384 + swq(wn * 64 + np * 16 + lrow8, ch);
            LDSM4(bfb[set][np][0], bfb[set][np][1], bfb[set][np][2], bfb[set][np][3], addr);
        }
#pragma unroll
        for (int mt = 0; mt < 4; ++mt) {
            uint32_t addr = base + swq(wm * 64 + mt * 16 + lrow8, ch);
            LDSM4(afb[set][mt][0], afb[set][mt][1], afb[set][mt][2], afb[set][mt][3], addr);
        }
    };
    auto frag_mma = [&](int set) {
#pragma unroll
        for (int mt = 0; mt < 4; ++mt)
#pragma unroll
            for (int np = 0; np < 4; ++np)
#pragma unroll
                for (int ni = 0; ni < 2; ++ni)
                    MMA_F16(acc[mt][np * 2 + ni],
                            afb[set][mt][0], afb[set][mt][1], afb[set][mt][2], afb[set][mt][3],
                            bfb[set][np][ni], bfb[set][np][ni + 2]);
    };

    const int T = K >> 6;                 // GEMM1: 8, GEMM2: 16
    load_stage(0, 0);
    load_stage(1, 64);
    CP_WAIT1();
    __syncthreads();                      // stage 0 resident
    uint32_t cbase = sbase;
    frag_load(0, cbase, 0);

    for (int t = 0; t < T; ++t) {
        if (t + 2 < T) load_stage((t + 2) % 3, (t + 2) << 6);
        else           CP_COMMIT();       // keep group count aligned for wait_group 1
        // kh 0..2: prefetch kh+1 into other set, mma(kh). All current-stage reads
        // complete at kh2's prefetch (kh3 frags then live in set 1).
#pragma unroll
        for (int kh = 0; kh < 3; ++kh) {
            frag_load((kh + 1) & 1, cbase, kh + 1);
            frag_mma(kh & 1);
        }
        if (t + 1 < T) {
            CP_WAIT1();
            __syncthreads();              // stage t+1 resident; current stage done being read
            cbase = sbase + ((t + 1) % 3) * STAGE_BYTES;
            frag_load(0, cbase, 0);       // next chunk kh0 -> set 0, hidden under kh3 MMAs
        }
        frag_mma(1);                      // kh3 (set 1)
    }

    // ---------------- epilogue ----------------
    const int mbase = m0 + wm * 64 + (lane >> 2);
    const int nbase = n0 + wn * 64 + (lane & 3) * 2;
#pragma unroll
    for (int mt = 0; mt < 4; ++mt) {
        int m = mbase + mt * 16;
        float s0 = 0.f, s1 = 0.f;
#pragma unroll
        for (int nt = 0; nt < 8; ++nt) {
            int n = nbase + nt * 8;
            float b0 = (n     < nbias) ? __ldg(&bias[n])     : 0.f;
            float b1 = (n + 1 < nbias) ? __ldg(&bias[n + 1]) : 0.f;
            float v00 = acc[mt][nt][0] + b0, v01 = acc[mt][nt][1] + b1;
            float v10 = acc[mt][nt][2] + b0, v11 = acc[mt][nt][3] + b1;
            if (WITH_NSQ) {
                s0 += v00 * v00 + v01 * v01;
                s1 += v10 * v10 + v11 * v11;
            } else {
                v00 = fmaxf(v00, 0.f); v01 = fmaxf(v01, 0.f);
                v10 = fmaxf(v10, 0.f); v11 = fmaxf(v11, 0.f);
            }
            if (m < Mc)
                *reinterpret_cast<uint32_t*>(&C[(size_t)m * ldc + n]) = pack_h2(v00, v01);
            if (m + 8 < Mc)
                *reinterpret_cast<uint32_t*>(&C[(size_t)(m + 8) * ldc + n]) = pack_h2(v10, v11);
        }
        if (WITH_NSQ) {
            s0 += __shfl_xor_sync(0xffffffffu, s0, 1);
            s0 += __shfl_xor_sync(0xffffffffu, s0, 2);
            s1 += __shfl_xor_sync(0xffffffffu, s1, 1);
            s1 += __shfl_xor_sync(0xffffffffu, s1, 2);
            if ((lane & 3) == 0) {
                size_t slab = (size_t)(blockIdx.x * 2 + wn) * VROWS;
                if (m < Mc)     g_nsq[slab + m]     = s0;
                if (m + 8 < Mc) g_nsq[slab + m + 8] = s1;
            }
        }
    }
}

// ---------------- norm finalize + gather ----------------
__global__ __launch_bounds__(256) void rsqrt_kernel() {
    int r = blockIdx.x * 256 + threadIdx.x;
    if (r >= g_Mc) return;
    float tot = 0.f;
#pragma unroll
    for (int s = 0; s < NSLAB; ++s) tot += g_nsq[(size_t)s * VROWS + r];
    g_invnorm[r] = 1.f / fmaxf(sqrtf(tot), 1e-12f);
}

// out[b] = sum_{l<len} Ec[inv[id]] * invnorm[inv[id]]; thread owns 8 consecutive cols.
// out rows have stride 2047 floats -> NOT 16B aligned for odd b; scalar stores only.
__global__ __launch_bounds__(256) void gather_kernel(const int* __restrict__ ingrs,
                                                     const int* __restrict__ lengths,
                                                     float* __restrict__ out) {
    __shared__ const uint4* sptr[SEQ];
    __shared__ float sscl[SEQ];
    const int b = blockIdx.x;
    const int t = threadIdx.x;
    if (t < SEQ) {
        int r = g_inv[ingrs[b * SEQ + t]];
        sptr[t] = reinterpret_cast<const uint4*>(&g_Ec[(size_t)r * DOUTP]);
        sscl[t] = g_invnorm[r];
    }
    __syncthreads();
    int len = lengths[b];
    if (len > SEQ) len = SEQ;

    float acc[8] = {0.f,0.f,0.f,0.f,0.f,0.f,0.f,0.f};
    int l = 0;
    for (; l + 2 <= len; l += 2) {                    // 2 independent loads in flight
        const float sA = sscl[l], sB = sscl[l + 1];
        uint4 vA = __ldg(&sptr[l][t]);
        uint4 vB = __ldg(&sptr[l + 1][t]);
        const __half2* hA = reinterpret_cast<const __half2*>(&vA);
        const __half2* hB = reinterpret_cast<const __half2*>(&vB);
#pragma unroll
        for (int q = 0; q < 4; ++q) {
            float2 fA = __half22float2(hA[q]);
            float2 fB = __half22float2(hB[q]);
            acc[q * 2]     += fA.x * sA + fB.x * sB;
            acc[q * 2 + 1] += fA.y * sA + fB.y * sB;
        }
    }
    if (l < len) {
        const float sA = sscl[l];
        uint4 vA = __ldg(&sptr[l][t]);
        const __half2* hA = reinterpret_cast<const __half2*>(&vA);
#pragma unroll
        for (int q = 0; q < 4; ++q) {
            float2 fA = __half22float2(hA[q]);
            acc[q * 2]     += fA.x * sA;
            acc[q * 2 + 1] += fA.y * sA;
        }
    }
    float* o = out + (size_t)b * DOUT;
    const int c0 = t * 8;
    const int lim = DOUT - c0;                  // last thread writes 7
#pragma unroll
    for (int j = 0; j < 8; ++j)
        if (j < lim) o[c0 + j] = acc[j];
}

// ---------------- launch ----------------
extern "C" void kernel_launch(void* const* d_in, const int* in_sizes, int n_in,
                              void* d_out, int out_size)
{
    const int*   ingrs   = (const int*)  d_in[0];
    const int*   lengths = (const int*)  d_in[1];
    const float* W1      = (const float*)d_in[2];
    const float* b1      = (const float*)d_in[3];
    const float* W2      = (const float*)d_in[4];
    const float* b2      = (const float*)d_in[5];
    const float* W3      = (const float*)d_in[6];
    const float* b3      = (const float*)d_in[7];
    float* out = (float*)d_out;

    __half *h1c, *w2t, *w3t, *h2c, *ec;
    cudaGetSymbolAddress((void**)&h1c, g_H1c);
    cudaGetSymbolAddress((void**)&w2t, g_W2T);
    cudaGetSymbolAddress((void**)&w3t, g_W3T);
    cudaGetSymbolAddress((void**)&h2c, g_H2c);
    cudaGetSymbolAddress((void**)&ec,  g_Ec);

    cudaFuncSetAttribute(hmma_gemm<true>,  cudaFuncAttributeMaxDynamicSharedMemorySize, GEMM_SMEM);
    cudaFuncSetAttribute(hmma_gemm<false>, cudaFuncAttributeMaxDynamicSharedMemorySize, GEMM_SMEM);

    // compaction: flags -> compact list -> inverse map -> Mc
    zero_flags<<<(VOCAB + 255) / 256, 256>>>();
    mark_used<<<(NB * SEQ + 255) / 256, 256>>>(ingrs, lengths);
    compact_ids<<<(VOCAB + 255) / 256, 256>>>();

    // fused prep: both weight transposes + compact H1 (MLP 2), one launch
    prep_all<<<PREP_TRANSPOSE_BLOCKS + VOCAB / 4, 256>>>(W1, b1, W2, W3, w2t, w3t);

    // GEMM1: H2c = relu(H1c @ W2^T + b2)   [Mc,1024] fp16
    dim3 g1(DH / 128, (VOCAB + 127) / 128);
    hmma_gemm<false><<<g1, 128, GEMM_SMEM>>>(h1c, w2t, b2, h2c, DIN, DH, DH);

    // GEMM2: Ec = H2c @ W3^T + b3          [Mc,2048 padded] fp16 + fp32 norm partials
    dim3 g2(DOUTP / 128, (VOCAB + 127) / 128);
    hmma_gemm<true><<<g2, 128, GEMM_SMEM>>>(h2c, w3t, b3, ec, DH, DOUTP, DOUT);

    rsqrt_kernel<<<(VOCAB + 255) / 256, 256>>>();
    gather_kernel<<<NB, 256>>>(ingrs, lengths, out);
}

// round 15
// speedup vs baseline: 1.0111x; 1.0111x over previous
#include <cuda_runtime.h>
#include <cuda_fp16.h>
#include <cstdint>

#define VOCAB 30000
#define VROWS 30080          // padded row count for partial-norm slabs
#define DIN   512
#define DH    1024
#define DOUT  2047
#define DOUTP 2048
#define NB    4096
#define SEQ   20
#define NSLAB 32             // 16 N-tiles x 2 wn warps (GEMM2)

// ---------------- scratch (__device__ globals; allocation-free rule) ----------------
__device__ int    g_flags[VOCAB];
__device__ int    g_compact[VOCAB];                // compact row -> vocab id
__device__ int    g_inv[VOCAB];                    // vocab id -> compact row
__device__ int    g_Mc;                            // number of used rows
__device__ __half g_H1c[(size_t)VOCAB * DIN];      // compact H1, fp16
__device__ __half g_W2T[(size_t)DH * DIN];         // [1024,512] N-major fp16
__device__ __half g_W3T[(size_t)DOUTP * DH];       // [2048,1024] fp16, row 2047 zero
__device__ __half g_H2c[(size_t)VOCAB * DH];       // compact H2, fp16
__device__ __half g_Ec[(size_t)VOCAB * DOUTP];     // compact E fp16, padded col 2047 == 0
__device__ float  g_nsq[(size_t)NSLAB * VROWS];    // per-slab partial sum-of-squares
__device__ float  g_invnorm[VOCAB];                // indexed by compact row

// ---------------- PTX helpers (generic PTX only; valid at compute_103) ----------------
static __device__ __forceinline__ uint32_t smem_to_u32(const void* p) {
    uint32_t a;
    asm("{ .reg .u64 t; cvta.to.shared.u64 t, %1; cvt.u32.u64 %0, t; }" : "=r"(a) : "l"(p));
    return a;
}
#define CP16(dst, src) \
    asm volatile("cp.async.cg.shared.global [%0], [%1], 16;" :: "r"(dst), "l"(src) : "memory")
#define CP_COMMIT() asm volatile("cp.async.commit_group;" ::: "memory")
#define CP_WAIT1()  asm volatile("cp.async.wait_group 1;" ::: "memory")

#define LDSM4(r0, r1, r2, r3, addr) \
    asm volatile("ldmatrix.sync.aligned.m8n8.x4.shared.b16 {%0,%1,%2,%3}, [%4];" \
        : "=r"(r0), "=r"(r1), "=r"(r2), "=r"(r3) : "r"(addr))

#define MMA_F16(d, a0, a1, a2, a3, b0, b1) \
    asm volatile("mma.sync.aligned.m16n8k16.row.col.f32.f16.f16.f32 " \
        "{%0,%1,%2,%3},{%4,%5,%6,%7},{%8,%9},{%0,%1,%2,%3};" \
        : "+f"((d)[0]), "+f"((d)[1]), "+f"((d)[2]), "+f"((d)[3]) \
        : "r"(a0), "r"(a1), "r"(a2), "r"(a3), "r"(b0), "r"(b1))

// swizzled byte offset inside a 128-row x 128-byte tile (16KB): 8 chunks of 16B per row
static __device__ __forceinline__ uint32_t swq(int row, int ch) {
    return (uint32_t)(row * 128 + ((ch ^ (row & 7)) << 4));
}
static __device__ __forceinline__ uint32_t pack_h2(float x, float y) {
    __half2 h = __floats2half2_rn(x, y);
    return *reinterpret_cast<uint32_t*>(&h);
}

// ---------------- compaction kernels ----------------
__global__ __launch_bounds__(256) void zero_flags() {
    int i = blockIdx.x * 256 + threadIdx.x;
    if (i < VOCAB) g_flags[i] = 0;
    if (i == 0) g_Mc = 0;
}
__global__ __launch_bounds__(256) void mark_used(const int* __restrict__ ingrs,
                                                 const int* __restrict__ lengths) {
    int i = blockIdx.x * 256 + threadIdx.x;
    if (i >= NB * SEQ) return;
    int b = i / SEQ, l = i - b * SEQ;
    if (l < lengths[b]) g_flags[ingrs[i]] = 1;
}
__global__ __launch_bounds__(256) void compact_ids() {
    int i = blockIdx.x * 256 + threadIdx.x;
    int flag = (i < VOCAB) ? g_flags[i] : 0;
    unsigned mask = __ballot_sync(0xffffffffu, flag);
    int lane = threadIdx.x & 31;
    int base = 0;
    if (lane == 0 && mask) base = atomicAdd(&g_Mc, __popc(mask));
    base = __shfl_sync(0xffffffffu, base, 0);
    if (flag) {
        int pos = base + __popc(mask & ((1u << lane) - 1u));
        g_compact[pos] = i;
        g_inv[i] = pos;
    }
}

// ---------------- fused prep: weight transposes + compact H1 (MLP 4), one launch ----------
// blocks [0,512): W2 transpose; [512,2560): W3 transpose; [2560, 2560+VOCAB/8): prep H1c.
#define PREP_TRANSPOSE_BLOCKS 2560
__global__ __launch_bounds__(256) void prep_all(const float* __restrict__ W1,
                                                const float* __restrict__ b1,
                                                const float* __restrict__ W2,
                                                const float* __restrict__ W3,
                                                __half* __restrict__ w2t,
                                                __half* __restrict__ w3t) {
    int bid = blockIdx.x;
    if (bid < PREP_TRANSPOSE_BLOCKS) {
        // -------- tiled transpose fp32 -> fp16 (rows n>=N zero) --------
        const float* src; __half* dst; int K, N, bx, by;
        if (bid < 512) { src = W2; dst = w2t; K = DIN; N = DH;   bx = bid & 31; by = bid >> 5; }
        else { bid -= 512; src = W3; dst = w3t; K = DH;  N = DOUT; bx = bid & 63; by = bid >> 6; }
        __shared__ float tile[32][33];
        const int tx = threadIdx.x & 31, ty = threadIdx.x >> 5;   // 32 x 8
        const int n0 = bx * 32, k0 = by * 32;
#pragma unroll
        for (int i = 0; i < 4; ++i) {
            int k = k0 + ty + i * 8, n = n0 + tx;
            tile[ty + i * 8][tx] = (n < N) ? src[(size_t)k * N + n] : 0.f;
        }
        __syncthreads();
#pragma unroll
        for (int i = 0; i < 4; ++i) {
            int n = n0 + ty + i * 8, k = k0 + tx;
            dst[(size_t)n * K + k] = __float2half_rn(tile[tx][ty + i * 8]);
        }
    } else {
        // -------- compact H1: 8 rows/block, 4 independent row loads per thread (MLP 4) ----
        bid -= PREP_TRANSPOSE_BLOCKS;
        const int Mc = g_Mc;
        const int rb = bid * 8;
        if (rb >= Mc) return;
        const int g  = threadIdx.x >> 7;                      // 0..1
        const int c4 = (threadIdx.x & 127) * 4;
        int   r[4];
        float4 w[4];
#pragma unroll
        for (int j = 0; j < 4; ++j) {
            r[j] = rb + g + j * 2;
            int rr = (r[j] < Mc) ? r[j] : Mc - 1;             // clamp keeps load legal
            int id = g_compact[rr];
            w[j] = __ldg(reinterpret_cast<const float4*>(&W1[(size_t)id * DIN + c4]));
        }
        float4 bb = __ldg(reinterpret_cast<const float4*>(&b1[c4]));
#pragma unroll
        for (int j = 0; j < 4; ++j) {
            if (r[j] >= Mc) break;
            __half h[4] = { __float2half_rn(fmaxf(w[j].x + bb.x, 0.f)),
                            __float2half_rn(fmaxf(w[j].y + bb.y, 0.f)),
                            __float2half_rn(fmaxf(w[j].z + bb.z, 0.f)),
                            __float2half_rn(fmaxf(w[j].w + bb.w, 0.f)) };
            *reinterpret_cast<uint2*>(&g_H1c[(size_t)r[j] * DIN + c4]) =
                *reinterpret_cast<uint2*>(h);
        }
    }
}

// ---------------- HMMA fp16 GEMM (64x64 warp tile, 4 warps, 2 CTA/SM) ----------------
// C = act(A @ B^T + bias), fp16 in/out. CTA tile 128x128, K-chunk 64,
// 3-stage cp.async pipeline (A|B @ 16KB each = 32KB/stage), 128 threads.
// Inner loop: round-13 ordering (R14 reorder was neutral-negative; reverted).
static constexpr int STAGE_BYTES = 32768;
static constexpr int GEMM_SMEM   = 3 * STAGE_BYTES;      // 96 KB

template <bool WITH_NSQ>   // true: no relu + write norm partials; false: relu
__global__ __launch_bounds__(128, 2)
void hmma_gemm(const __half* __restrict__ Af, const __half* __restrict__ Bf,
               const float* __restrict__ bias,
               __half* __restrict__ C,
               int K, int ldc, int nbias)
{
    const int m0 = blockIdx.y * 128;
    const int Mc = g_Mc;
    if (m0 >= Mc) return;                 // uniform whole-CTA exit

    extern __shared__ __align__(128) uint8_t smem[];
    const uint32_t sbase = smem_to_u32(smem);
    const int tid  = threadIdx.x;
    const int lane = tid & 31;
    const int wid  = tid >> 5;            // 0..3
    const int wm   = wid & 1;             // m block of 64
    const int wn   = wid >> 1;            // n block of 64
    const int n0   = blockIdx.x * 128;

    const int lmat  = lane >> 3;
    const int lrow8 = ((lmat & 1) << 3) + (lane & 7);
    const int lchb  = lmat >> 1;          // 16B chunk parity within a k16

    float acc[4][8][4];
#pragma unroll
    for (int a = 0; a < 4; ++a)
#pragma unroll
        for (int b = 0; b < 8; ++b)
#pragma unroll
            for (int c = 0; c < 4; ++c) acc[a][b][c] = 0.f;

    auto load_stage = [&](int s, int k0) {
        const uint32_t base = sbase + s * STAGE_BYTES;
#pragma unroll
        for (int p = 0; p < 8; ++p) {
            int idx = p * 128 + tid;            // 0..1023
            int row = idx >> 3;                 // 0..127
            int ch  = idx & 7;                  // 16B chunk in 128B row
            uint32_t doff = swq(row, ch);
            int gm = m0 + row; if (gm > Mc - 1) gm = Mc - 1;  // clamp; rows >= Mc never stored
            CP16(base +         doff, Af + (size_t)gm * K + k0 + ch * 8);
            CP16(base + 16384 + doff, Bf + (size_t)(n0 + row) * K + k0 + ch * 8);
        }
        CP_COMMIT();
    };

    // fragment double buffers (A 4 tiles + B 4 tiles per k16)
    uint32_t afb[2][4][4], bfb[2][4][4];

    auto frag_load = [&](int set, uint32_t base, int kh) {
        const int ch = kh * 2 + lchb;
#pragma unroll
        for (int np = 0; np < 4; ++np) {
            uint32_t addr = base + 16384 + swq(wn * 64 + np * 16 + lrow8, ch);
            LDSM4(bfb[set][np][0], bfb[set][np][1], bfb[set][np][2], bfb[set][np][3], addr);
        }
#pragma unroll
        for (int mt = 0; mt < 4; ++mt) {
            uint32_t addr = base + swq(wm * 64 + mt * 16 + lrow8, ch);
            LDSM4(afb[set][mt][0], afb[set][mt][1], afb[set][mt][2], afb[set][mt][3], addr);
        }
    };
    auto frag_mma = [&](int set) {
#pragma unroll
        for (int mt = 0; mt < 4; ++mt)
#pragma unroll
            for (int np = 0; np < 4; ++np)
#pragma unroll
                for (int ni = 0; ni < 2; ++ni)
                    MMA_F16(acc[mt][np * 2 + ni],
                            afb[set][mt][0], afb[set][mt][1], afb[set][mt][2], afb[set][mt][3],
                            bfb[set][np][ni], bfb[set][np][ni + 2]);
    };

    const int T = K >> 6;                 // GEMM1: 8, GEMM2: 16
    load_stage(0, 0);
    load_stage(1, 64);
    CP_WAIT1();
    __syncthreads();                      // stage 0 resident
    uint32_t cbase = sbase;
    frag_load(0, cbase, 0);

    for (int t = 0; t < T; ++t) {
        if (t + 2 < T) load_stage((t + 2) % 3, (t + 2) << 6);
        else           CP_COMMIT();       // keep group count aligned for wait_group 1
#pragma unroll
        for (int kh = 0; kh < 4; ++kh) {
            if (kh < 3) frag_load((kh + 1) & 1, cbase, kh + 1);   // prefetch next k16
            frag_mma(kh & 1);
        }
        if (t + 1 < T) {
            CP_WAIT1();
            __syncthreads();              // stage t+1 resident
            cbase = sbase + ((t + 1) % 3) * STAGE_BYTES;
            frag_load(0, cbase, 0);
        }
    }

    // ---------------- epilogue ----------------
    const int mbase = m0 + wm * 64 + (lane >> 2);
    const int nbase = n0 + wn * 64 + (lane & 3) * 2;
#pragma unroll
    for (int mt = 0; mt < 4; ++mt) {
        int m = mbase + mt * 16;
        float s0 = 0.f, s1 = 0.f;
#pragma unroll
        for (int nt = 0; nt < 8; ++nt) {
            int n = nbase + nt * 8;
            float b0 = (n     < nbias) ? __ldg(&bias[n])     : 0.f;
            float b1 = (n + 1 < nbias) ? __ldg(&bias[n + 1]) : 0.f;
            float v00 = acc[mt][nt][0] + b0, v01 = acc[mt][nt][1] + b1;
            float v10 = acc[mt][nt][2] + b0, v11 = acc[mt][nt][3] + b1;
            if (WITH_NSQ) {
                s0 += v00 * v00 + v01 * v01;
                s1 += v10 * v10 + v11 * v11;
            } else {
                v00 = fmaxf(v00, 0.f); v01 = fmaxf(v01, 0.f);
                v10 = fmaxf(v10, 0.f); v11 = fmaxf(v11, 0.f);
            }
            if (m < Mc)
                *reinterpret_cast<uint32_t*>(&C[(size_t)m * ldc + n]) = pack_h2(v00, v01);
            if (m + 8 < Mc)
                *reinterpret_cast<uint32_t*>(&C[(size_t)(m + 8) * ldc + n]) = pack_h2(v10, v11);
        }
        if (WITH_NSQ) {
            s0 += __shfl_xor_sync(0xffffffffu, s0, 1);
            s0 += __shfl_xor_sync(0xffffffffu, s0, 2);
            s1 += __shfl_xor_sync(0xffffffffu, s1, 1);
            s1 += __shfl_xor_sync(0xffffffffu, s1, 2);
            if ((lane & 3) == 0) {
                size_t slab = (size_t)(blockIdx.x * 2 + wn) * VROWS;
                if (m < Mc)     g_nsq[slab + m]     = s0;
                if (m + 8 < Mc) g_nsq[slab + m + 8] = s1;
            }
        }
    }
}

// ---------------- norm finalize + gather ----------------
__global__ __launch_bounds__(256) void rsqrt_kernel() {
    int r = blockIdx.x * 256 + threadIdx.x;
    if (r >= g_Mc) return;
    float tot = 0.f;
#pragma unroll
    for (int s = 0; s < NSLAB; ++s) tot += g_nsq[(size_t)s * VROWS + r];
    g_invnorm[r] = 1.f / fmaxf(sqrtf(tot), 1e-12f);
}

// out[b] = sum_{l<len} Ec[inv[id]] * invnorm[inv[id]]; thread owns 8 consecutive cols.
// out rows have stride 2047 floats -> NOT 16B aligned for odd b; scalar stores only.
__global__ __launch_bounds__(256) void gather_kernel(const int* __restrict__ ingrs,
                                                     const int* __restrict__ lengths,
                                                     float* __restrict__ out) {
    __shared__ const uint4* sptr[SEQ];
    __shared__ float sscl[SEQ];
    const int b = blockIdx.x;
    const int t = threadIdx.x;
    if (t < SEQ) {
        int r = g_inv[ingrs[b * SEQ + t]];
        sptr[t] = reinterpret_cast<const uint4*>(&g_Ec[(size_t)r * DOUTP]);
        sscl[t] = g_invnorm[r];
    }
    __syncthreads();
    int len = lengths[b];
    if (len > SEQ) len = SEQ;

    float acc[8] = {0.f,0.f,0.f,0.f,0.f,0.f,0.f,0.f};
    int l = 0;
    for (; l + 2 <= len; l += 2) {                    // 2 independent loads in flight
        const float sA = sscl[l], sB = sscl[l + 1];
        uint4 vA = __ldg(&sptr[l][t]);
        uint4 vB = __ldg(&sptr[l + 1][t]);
        const __half2* hA = reinterpret_cast<const __half2*>(&vA);
        const __half2* hB = reinterpret_cast<const __half2*>(&vB);
#pragma unroll
        for (int q = 0; q < 4; ++q) {
            float2 fA = __half22float2(hA[q]);
            float2 fB = __half22float2(hB[q]);
            acc[q * 2]     += fA.x * sA + fB.x * sB;
            acc[q * 2 + 1] += fA.y * sA + fB.y * sB;
        }
    }
    if (l < len) {
        const float sA = sscl[l];
        uint4 vA = __ldg(&sptr[l][t]);
        const __half2* hA = reinterpret_cast<const __half2*>(&vA);
#pragma unroll
        for (int q = 0; q < 4; ++q) {
            float2 fA = __half22float2(hA[q]);
            acc[q * 2]     += fA.x * sA;
            acc[q * 2 + 1] += fA.y * sA;
        }
    }
    float* o = out + (size_t)b * DOUT;
    const int c0 = t * 8;
    const int lim = DOUT - c0;                  // last thread writes 7
#pragma unroll
    for (int j = 0; j < 8; ++j)
        if (j < lim) o[c0 + j] = acc[j];
}

// ---------------- launch ----------------
extern "C" void kernel_launch(void* const* d_in, const int* in_sizes, int n_in,
                              void* d_out, int out_size)
{
    const int*   ingrs   = (const int*)  d_in[0];
    const int*   lengths = (const int*)  d_in[1];
    const float* W1      = (const float*)d_in[2];
    const float* b1      = (const float*)d_in[3];
    const float* W2      = (const float*)d_in[4];
    const float* b2      = (const float*)d_in[5];
    const float* W3      = (const float*)d_in[6];
    const float* b3      = (const float*)d_in[7];
    float* out = (float*)d_out;

    __half *h1c, *w2t, *w3t, *h2c, *ec;
    cudaGetSymbolAddress((void**)&h1c, g_H1c);
    cudaGetSymbolAddress((void**)&w2t, g_W2T);
    cudaGetSymbolAddress((void**)&w3t, g_W3T);
    cudaGetSymbolAddress((void**)&h2c, g_H2c);
    cudaGetSymbolAddress((void**)&ec,  g_Ec);

    cudaFuncSetAttribute(hmma_gemm<true>,  cudaFuncAttributeMaxDynamicSharedMemorySize, GEMM_SMEM);
    cudaFuncSetAttribute(hmma_gemm<false>, cudaFuncAttributeMaxDynamicSharedMemorySize, GEMM_SMEM);

    // compaction: flags -> compact list -> inverse map -> Mc
    zero_flags<<<(VOCAB + 255) / 256, 256>>>();
    mark_used<<<(NB * SEQ + 255) / 256, 256>>>(ingrs, lengths);
    compact_ids<<<(VOCAB + 255) / 256, 256>>>();

    // fused prep: both weight transposes + compact H1 (MLP 4), one launch
    prep_all<<<PREP_TRANSPOSE_BLOCKS + VOCAB / 8, 256>>>(W1, b1, W2, W3, w2t, w3t);

    // GEMM1: H2c = relu(H1c @ W2^T + b2)   [Mc,1024] fp16
    dim3 g1(DH / 128, (VOCAB + 127) / 128);
    hmma_gemm<false><<<g1, 128, GEMM_SMEM>>>(h1c, w2t, b2, h2c, DIN, DH, DH);

    // GEMM2: Ec = H2c @ W3^T + b3          [Mc,2048 padded] fp16 + fp32 norm partials
    dim3 g2(DOUTP / 128, (VOCAB + 127) / 128);
    hmma_gemm<true><<<g2, 128, GEMM_SMEM>>>(h2c, w3t, b3, ec, DH, DOUTP, DOUT);

    rsqrt_kernel<<<(VOCAB + 255) / 256, 256>>>();
    gather_kernel<<<NB, 256>>>(ingrs, lengths, out);
}